// round 3
// baseline (speedup 1.0000x reference)
#include <cuda_runtime.h>
#include <cuda_bf16.h>

#define NNODES 512
#define NIN    256
#define NOUT   256

// Scratch: A[i,o] = x[i] @ W[:, :256]^T + b ; B[i,o] = x[i] @ W[:, 256:]^T
__device__ float g_A[NNODES * NOUT];
__device__ float g_B[NNODES * NOUT];

// ---------------------------------------------------------------------------
// Kernel 1: two small fp32 GEMMs (half=0 -> A with bias, half=1 -> B).
// C[i,o] = sum_k x[i,k] * W[o, half*256 + k]   (both operands K-contiguous, NT)
// Tiles: BM=32 (i), BN=64 (o), BK=32. 256 threads, micro-tile 2(i) x 4(o).
// ---------------------------------------------------------------------------
__global__ void __launch_bounds__(256)
gemm_ab_kernel(const float* __restrict__ x,
               const float* __restrict__ W,
               const float* __restrict__ b)
{
    const int half = blockIdx.z;              // 0: A-half, 1: B-half
    const int i0   = blockIdx.y * 32;
    const int o0   = blockIdx.x * 64;
    const int woff = half * NIN;              // column offset into W

    __shared__ __align__(16) float xs[32 * 34];   // [k][i], padded stride 34
    __shared__ __align__(16) float ws[32 * 68];   // [k][o], padded stride 68

    const int tid = threadIdx.x;
    const int tx  = tid & 15;   // o-thread (4 cols each)
    const int ty  = tid >> 4;   // i-thread (2 rows each)

    float acc[2][4] = {{0.f,0.f,0.f,0.f},{0.f,0.f,0.f,0.f}};

    for (int k0 = 0; k0 < NIN; k0 += 32) {
        // ---- load x tile [32 i x 32 k], transposed into xs[k][i] ----
        {
            int r  = tid >> 3;       // 0..31 : i-row
            int kq = tid & 7;        // 0..7  : k quad
            float4 v = *reinterpret_cast<const float4*>(
                &x[(i0 + r) * NIN + k0 + kq * 4]);
            xs[(kq * 4 + 0) * 34 + r] = v.x;
            xs[(kq * 4 + 1) * 34 + r] = v.y;
            xs[(kq * 4 + 2) * 34 + r] = v.z;
            xs[(kq * 4 + 3) * 34 + r] = v.w;
        }
        // ---- load W tile [64 o x 32 k], transposed into ws[k][o] ----
        #pragma unroll
        for (int s = 0; s < 2; s++) {
            int idx = tid + s * 256;
            int oo  = idx >> 3;      // 0..63 : o-row
            int kq  = idx & 7;       // 0..7  : k quad
            float4 v = *reinterpret_cast<const float4*>(
                &W[(o0 + oo) * (2 * NIN) + woff + k0 + kq * 4]);
            ws[(kq * 4 + 0) * 68 + oo] = v.x;
            ws[(kq * 4 + 1) * 68 + oo] = v.y;
            ws[(kq * 4 + 2) * 68 + oo] = v.z;
            ws[(kq * 4 + 3) * 68 + oo] = v.w;
        }
        __syncthreads();

        #pragma unroll
        for (int kk = 0; kk < 32; kk++) {
            float2 a  = *reinterpret_cast<const float2*>(&xs[kk * 34 + ty * 2]);
            float4 wq = *reinterpret_cast<const float4*>(&ws[kk * 68 + tx * 4]);
            acc[0][0] += a.x * wq.x;
            acc[0][1] += a.x * wq.y;
            acc[0][2] += a.x * wq.z;
            acc[0][3] += a.x * wq.w;
            acc[1][0] += a.y * wq.x;
            acc[1][1] += a.y * wq.y;
            acc[1][2] += a.y * wq.z;
            acc[1][3] += a.y * wq.w;
        }
        __syncthreads();
    }

    // ---- epilogue: fold bias into the A-half only ----
    float4 bias = make_float4(0.f, 0.f, 0.f, 0.f);
    if (half == 0)
        bias = *reinterpret_cast<const float4*>(&b[o0 + tx * 4]);

    float* dst = (half == 0) ? g_A : g_B;
    #pragma unroll
    for (int r = 0; r < 2; r++) {
        int i = i0 + ty * 2 + r;
        float4 outv = make_float4(acc[r][0] + bias.x,
                                  acc[r][1] + bias.y,
                                  acc[r][2] + bias.z,
                                  acc[r][3] + bias.w);
        *reinterpret_cast<float4*>(&dst[i * NOUT + o0 + tx * 4]) = outv;
    }
}

// ---------------------------------------------------------------------------
// Kernel 2: symmetric tile writer.
// Grid 32x32 tiles of 16x16 (i,j); lower-triangle tiles exit immediately.
// A block (bi <= bj) loads A[i-tile], B[j-tile] into smem, computes
// v = A[i] + B[j] once, writes it to out[i,j,:] AND out[j,i,:].
// Diagonal tiles (bi==bj) handle ii<jj pairs + zero the diagonal.
// ---------------------------------------------------------------------------
__global__ void __launch_bounds__(256)
sym_writer_kernel(float* __restrict__ out)
{
    const int bj = blockIdx.x;
    const int bi = blockIdx.y;
    if (bi > bj) return;

    const int i0 = bi * 16;
    const int j0 = bj * 16;

    __shared__ __align__(16) float sA[16 * 256];
    __shared__ __align__(16) float sB[16 * 256];

    const int tid = threadIdx.x;

    // load A rows i0..i0+15 and B rows j0..j0+15 (float4, fully coalesced)
    #pragma unroll
    for (int s = 0; s < 4; s++) {
        int idx = tid + s * 256;       // float4 slot 0..1023
        int r   = idx >> 6;            // row 0..15
        int c4  = idx & 63;            // float4 column 0..63
        *reinterpret_cast<float4*>(&sA[r * 256 + c4 * 4]) =
            *reinterpret_cast<const float4*>(&g_A[(i0 + r) * 256 + c4 * 4]);
        *reinterpret_cast<float4*>(&sB[r * 256 + c4 * 4]) =
            *reinterpret_cast<const float4*>(&g_B[(j0 + r) * 256 + c4 * 4]);
    }
    __syncthreads();

    const int  lane_c = tid & 63;      // float4 channel index (c = lane_c*4)
    const int  lane_p = tid >> 6;      // pair sub-index 0..3
    const bool diag   = (bi == bj);
    const int  coff   = lane_c * 4;

    #pragma unroll 4
    for (int it = 0; it < 64; it++) {
        int p  = it * 4 + lane_p;      // pair index 0..255
        int ii = p >> 4;
        int jj = p & 15;

        float4 a  = *reinterpret_cast<const float4*>(&sA[ii * 256 + coff]);
        float4 bb = *reinterpret_cast<const float4*>(&sB[jj * 256 + coff]);
        float4 v  = make_float4(a.x + bb.x, a.y + bb.y, a.z + bb.z, a.w + bb.w);

        int i = i0 + ii;
        int j = j0 + jj;
        size_t idx_ij = ((size_t)i * NNODES + j) * NOUT + coff;
        size_t idx_ji = ((size_t)j * NNODES + i) * NOUT + coff;

        if (!diag) {
            *reinterpret_cast<float4*>(&out[idx_ij]) = v;
            *reinterpret_cast<float4*>(&out[idx_ji]) = v;
        } else {
            if (ii < jj) {
                *reinterpret_cast<float4*>(&out[idx_ij]) = v;
                *reinterpret_cast<float4*>(&out[idx_ji]) = v;
            } else if (ii == jj) {
                *reinterpret_cast<float4*>(&out[idx_ij]) =
                    make_float4(0.f, 0.f, 0.f, 0.f);
            }
            // ii > jj: covered by the (jj, ii) pair's mirrored write
        }
    }
}

extern "C" void kernel_launch(void* const* d_in, const int* in_sizes, int n_in,
                              void* d_out, int out_size)
{
    const float* x = (const float*)d_in[0];   // [512, 256]
    const float* W = (const float*)d_in[1];   // [256, 512]
    const float* b = (const float*)d_in[2];   // [256]
    float* out = (float*)d_out;               // [512, 512, 256]

    // Kernel 1: A = x@W1^T + b, B = x@W2^T   (128 blocks)
    gemm_ab_kernel<<<dim3(4, 16, 2), 256>>>(x, W, b);

    // Kernel 2: symmetric scatter of A[i]+B[j] into out (528 active blocks)
    sym_writer_kernel<<<dim3(32, 32), 256>>>(out);
}

// round 4
// speedup vs baseline: 1.2192x; 1.2192x over previous
#include <cuda_runtime.h>
#include <cuda_bf16.h>

#define NNODES 512
#define NIN    256
#define NOUT   256
#define NT     32      // 512/16 node tiles
#define TS     16      // writer tile size

// Split-K partial buffers: A = A0 + A1 (bias folded into A0), B = B0 + B1.
__device__ float g_A0[NNODES * NOUT];
__device__ float g_A1[NNODES * NOUT];
__device__ float g_B0[NNODES * NOUT];
__device__ float g_B1[NNODES * NOUT];

// ---------------------------------------------------------------------------
// Kernel 1: split-K GEMM partials.
//   z = half*2 + ks :  half selects A/B weight column block, ks selects the
//   K chunk [ks*128, ks*128+128).
//   C_part[i,o] = sum_{k in chunk} x[i,k] * W[o, half*256 + k]
// Tiles: BM=32(i) x BN=32(o) x BK=32, 128 threads, micro-tile 2(i) x 4(o).
// Grid: 8 x 16 x 4 = 512 blocks -> ~14 warps/SM, LDS latency hidden.
// ---------------------------------------------------------------------------
__global__ void __launch_bounds__(128)
gemm_ab_kernel(const float* __restrict__ x,
               const float* __restrict__ W,
               const float* __restrict__ b)
{
    const int z    = blockIdx.z;
    const int half = z >> 1;                  // 0: A, 1: B
    const int ks   = z & 1;                   // K-split index
    const int i0   = blockIdx.y * 32;
    const int o0   = blockIdx.x * 32;
    const int kbase = ks * 128;               // global k chunk start
    const int woff  = half * NIN;             // column offset into W rows

    __shared__ __align__(16) float xs[32 * 34];  // [k][i], stride 34 (float2 ok)
    __shared__ __align__(16) float ws[32 * 36];  // [k][o], stride 36 (float4 ok)

    const int tid = threadIdx.x;
    const int tx  = tid & 7;    // o-thread: 4 cols each  -> 32 o
    const int ty  = tid >> 3;   // i-thread: 2 rows each  -> 32 i

    float acc[2][4] = {{0.f,0.f,0.f,0.f},{0.f,0.f,0.f,0.f}};

    for (int k0 = 0; k0 < 128; k0 += 32) {
        // ---- load x tile [32 i x 32 k] transposed -> xs[k][i] ----
        #pragma unroll
        for (int s = 0; s < 2; s++) {
            int idx = tid + s * 128;          // 0..255 float4 slots
            int r   = idx >> 3;               // i row 0..31
            int kq  = idx & 7;                // k quad 0..7
            float4 v = *reinterpret_cast<const float4*>(
                &x[(i0 + r) * NIN + kbase + k0 + kq * 4]);
            xs[(kq * 4 + 0) * 34 + r] = v.x;
            xs[(kq * 4 + 1) * 34 + r] = v.y;
            xs[(kq * 4 + 2) * 34 + r] = v.z;
            xs[(kq * 4 + 3) * 34 + r] = v.w;
        }
        // ---- load W tile [32 o x 32 k] transposed -> ws[k][o] ----
        #pragma unroll
        for (int s = 0; s < 2; s++) {
            int idx = tid + s * 128;
            int oo  = idx >> 3;               // o row 0..31
            int kq  = idx & 7;
            float4 v = *reinterpret_cast<const float4*>(
                &W[(o0 + oo) * (2 * NIN) + woff + kbase + k0 + kq * 4]);
            ws[(kq * 4 + 0) * 36 + oo] = v.x;
            ws[(kq * 4 + 1) * 36 + oo] = v.y;
            ws[(kq * 4 + 2) * 36 + oo] = v.z;
            ws[(kq * 4 + 3) * 36 + oo] = v.w;
        }
        __syncthreads();

        #pragma unroll
        for (int kk = 0; kk < 32; kk++) {
            float2 a  = *reinterpret_cast<const float2*>(&xs[kk * 34 + ty * 2]);
            float4 wq = *reinterpret_cast<const float4*>(&ws[kk * 36 + tx * 4]);
            acc[0][0] += a.x * wq.x;
            acc[0][1] += a.x * wq.y;
            acc[0][2] += a.x * wq.z;
            acc[0][3] += a.x * wq.w;
            acc[1][0] += a.y * wq.x;
            acc[1][1] += a.y * wq.y;
            acc[1][2] += a.y * wq.z;
            acc[1][3] += a.y * wq.w;
        }
        __syncthreads();
    }

    // ---- epilogue: bias folded only into the (half=0, ks=0) partial ----
    float4 bias = make_float4(0.f, 0.f, 0.f, 0.f);
    if (half == 0 && ks == 0)
        bias = *reinterpret_cast<const float4*>(&b[o0 + tx * 4]);

    float* dst = (half == 0) ? (ks == 0 ? g_A0 : g_A1)
                             : (ks == 0 ? g_B0 : g_B1);
    #pragma unroll
    for (int r = 0; r < 2; r++) {
        int i = i0 + ty * 2 + r;
        float4 outv = make_float4(acc[r][0] + bias.x,
                                  acc[r][1] + bias.y,
                                  acc[r][2] + bias.z,
                                  acc[r][3] + bias.w);
        *reinterpret_cast<float4*>(&dst[i * NOUT + o0 + tx * 4]) = outv;
    }
}

// ---------------------------------------------------------------------------
// Kernel 2: symmetric tile writer, all 1024 blocks active.
//   Lower-triangle blocks (bi > bj) are remapped to (31-bi, 31-bj) — a
//   bijection onto the strict upper triangle — and write ONLY the mirror
//   copy out[j,i]. Original strict-upper blocks write out[i,j]. Diagonal
//   tiles (one block each) write both halves + zero diagonal.
//   A-row register caching: 1 LDS(A) per 16 { LDS(B) + STG } iterations.
//   Streaming stores (__stcs): output is write-once, keep it out of L2.
// ---------------------------------------------------------------------------
__global__ void __launch_bounds__(256)
sym_writer_kernel(float* __restrict__ out)
{
    int bj = blockIdx.x;
    int bi = blockIdx.y;
    bool mirror = false;
    if (bi > bj) {                    // remap lower -> strict upper twin
        bi = (NT - 1) - bi;
        bj = (NT - 1) - bj;
        mirror = true;
    }
    const bool diag = (bi == bj);
    const int i0 = bi * TS;
    const int j0 = bj * TS;

    __shared__ __align__(16) float sA[TS * NOUT];
    __shared__ __align__(16) float sB[TS * NOUT];

    const int tid = threadIdx.x;

    // ---- load A = A0+A1 rows i0.., B = B0+B1 rows j0.. (float4 coalesced) --
    #pragma unroll
    for (int s = 0; s < 4; s++) {
        int idx = tid + s * 256;      // float4 slot 0..1023
        int r   = idx >> 6;           // row 0..15
        int cc  = (idx & 63) * 4;     // float col
        float4 a0 = *reinterpret_cast<const float4*>(&g_A0[(i0 + r) * NOUT + cc]);
        float4 a1 = *reinterpret_cast<const float4*>(&g_A1[(i0 + r) * NOUT + cc]);
        *reinterpret_cast<float4*>(&sA[r * NOUT + cc]) =
            make_float4(a0.x + a1.x, a0.y + a1.y, a0.z + a1.z, a0.w + a1.w);
        float4 b0 = *reinterpret_cast<const float4*>(&g_B0[(j0 + r) * NOUT + cc]);
        float4 b1 = *reinterpret_cast<const float4*>(&g_B1[(j0 + r) * NOUT + cc]);
        *reinterpret_cast<float4*>(&sB[r * NOUT + cc]) =
            make_float4(b0.x + b1.x, b0.y + b1.y, b0.z + b1.z, b0.w + b1.w);
    }
    __syncthreads();

    const int c  = (tid & 63) * 4;    // channel offset (float4)
    const int ip = tid >> 6;          // ii sub-index 0..3

    if (!diag) {
        #pragma unroll
        for (int ob = 0; ob < 4; ob++) {
            const int ii = ob * 4 + ip;
            const float4 a = *reinterpret_cast<const float4*>(&sA[ii * NOUT + c]);
            const int i = i0 + ii;
            #pragma unroll 4
            for (int jj = 0; jj < TS; jj++) {
                float4 bb = *reinterpret_cast<const float4*>(&sB[jj * NOUT + c]);
                float4 v  = make_float4(a.x + bb.x, a.y + bb.y,
                                        a.z + bb.z, a.w + bb.w);
                int j = j0 + jj;
                size_t idx = mirror
                    ? (((size_t)j * NNODES + i) * NOUT + c)
                    : (((size_t)i * NNODES + j) * NOUT + c);
                __stcs(reinterpret_cast<float4*>(&out[idx]), v);
            }
        }
    } else {
        // diagonal tile: single block writes both copies + zero diagonal
        #pragma unroll
        for (int ob = 0; ob < 4; ob++) {
            const int ii = ob * 4 + ip;
            const float4 a = *reinterpret_cast<const float4*>(&sA[ii * NOUT + c]);
            const int i = i0 + ii;
            for (int jj = ii + 1; jj < TS; jj++) {
                float4 bb = *reinterpret_cast<const float4*>(&sB[jj * NOUT + c]);
                float4 v  = make_float4(a.x + bb.x, a.y + bb.y,
                                        a.z + bb.z, a.w + bb.w);
                int j = j0 + jj;
                __stcs(reinterpret_cast<float4*>(
                    &out[((size_t)i * NNODES + j) * NOUT + c]), v);
                __stcs(reinterpret_cast<float4*>(
                    &out[((size_t)j * NNODES + i) * NOUT + c]), v);
            }
            __stcs(reinterpret_cast<float4*>(
                &out[((size_t)i * NNODES + i) * NOUT + c]),
                make_float4(0.f, 0.f, 0.f, 0.f));
        }
    }
}

extern "C" void kernel_launch(void* const* d_in, const int* in_sizes, int n_in,
                              void* d_out, int out_size)
{
    const float* x = (const float*)d_in[0];   // [512, 256]
    const float* W = (const float*)d_in[1];   // [256, 512]
    const float* b = (const float*)d_in[2];   // [256]
    float* out = (float*)d_out;               // [512, 512, 256]

    // Kernel 1: split-K partials (512 blocks x 128 threads)
    gemm_ab_kernel<<<dim3(8, 16, 4), 128>>>(x, W, b);

    // Kernel 2: symmetric scatter, all 1024 blocks active
    sym_writer_kernel<<<dim3(NT, NT), 256>>>(out);
}

// round 7
// speedup vs baseline: 1.2616x; 1.0347x over previous
#include <cuda_runtime.h>
#include <cuda_bf16.h>

#define NNODES 512
#define NIN    256
#define NOUT   256
#define NT     32      // 512/16 node tiles
#define TS     16      // writer tile size

// Split-K partial buffers: A = A0 + A1 (bias folded into A0), B = B0 + B1.
__device__ float g_A0[NNODES * NOUT];
__device__ float g_A1[NNODES * NOUT];
__device__ float g_B0[NNODES * NOUT];
__device__ float g_B1[NNODES * NOUT];

// ---------------------------------------------------------------------------
// Kernel 1: split-K GEMM partials (unchanged from R4, + PDL trigger).
// ---------------------------------------------------------------------------
__global__ void __launch_bounds__(128)
gemm_ab_kernel(const float* __restrict__ x,
               const float* __restrict__ W,
               const float* __restrict__ b)
{
    const int z    = blockIdx.z;
    const int half = z >> 1;                  // 0: A, 1: B
    const int ks   = z & 1;                   // K-split index
    const int i0   = blockIdx.y * 32;
    const int o0   = blockIdx.x * 32;
    const int kbase = ks * 128;
    const int woff  = half * NIN;

    __shared__ __align__(16) float xs[32 * 34];  // [k][i]
    __shared__ __align__(16) float ws[32 * 36];  // [k][o]

    const int tid = threadIdx.x;
    const int tx  = tid & 7;    // o-thread: 4 cols
    const int ty  = tid >> 3;   // i-thread: 2 rows

    float acc[2][4] = {{0.f,0.f,0.f,0.f},{0.f,0.f,0.f,0.f}};

    for (int k0 = 0; k0 < 128; k0 += 32) {
        #pragma unroll
        for (int s = 0; s < 2; s++) {
            int idx = tid + s * 128;
            int r   = idx >> 3;
            int kq  = idx & 7;
            float4 v = *reinterpret_cast<const float4*>(
                &x[(i0 + r) * NIN + kbase + k0 + kq * 4]);
            xs[(kq * 4 + 0) * 34 + r] = v.x;
            xs[(kq * 4 + 1) * 34 + r] = v.y;
            xs[(kq * 4 + 2) * 34 + r] = v.z;
            xs[(kq * 4 + 3) * 34 + r] = v.w;
        }
        #pragma unroll
        for (int s = 0; s < 2; s++) {
            int idx = tid + s * 128;
            int oo  = idx >> 3;
            int kq  = idx & 7;
            float4 v = *reinterpret_cast<const float4*>(
                &W[(o0 + oo) * (2 * NIN) + woff + kbase + k0 + kq * 4]);
            ws[(kq * 4 + 0) * 36 + oo] = v.x;
            ws[(kq * 4 + 1) * 36 + oo] = v.y;
            ws[(kq * 4 + 2) * 36 + oo] = v.z;
            ws[(kq * 4 + 3) * 36 + oo] = v.w;
        }
        __syncthreads();

        #pragma unroll
        for (int kk = 0; kk < 32; kk++) {
            float2 a  = *reinterpret_cast<const float2*>(&xs[kk * 34 + ty * 2]);
            float4 wq = *reinterpret_cast<const float4*>(&ws[kk * 36 + tx * 4]);
            acc[0][0] += a.x * wq.x;
            acc[0][1] += a.x * wq.y;
            acc[0][2] += a.x * wq.z;
            acc[0][3] += a.x * wq.w;
            acc[1][0] += a.y * wq.x;
            acc[1][1] += a.y * wq.y;
            acc[1][2] += a.y * wq.z;
            acc[1][3] += a.y * wq.w;
        }
        __syncthreads();
    }

    float4 bias = make_float4(0.f, 0.f, 0.f, 0.f);
    if (half == 0 && ks == 0)
        bias = *reinterpret_cast<const float4*>(&b[o0 + tx * 4]);

    float* dst = (half == 0) ? (ks == 0 ? g_A0 : g_A1)
                             : (ks == 0 ? g_B0 : g_B1);
    #pragma unroll
    for (int r = 0; r < 2; r++) {
        int i = i0 + ty * 2 + r;
        float4 outv = make_float4(acc[r][0] + bias.x,
                                  acc[r][1] + bias.y,
                                  acc[r][2] + bias.z,
                                  acc[r][3] + bias.w);
        *reinterpret_cast<float4*>(&dst[i * NOUT + o0 + tx * 4]) = outv;
    }

    // PDL: writes above are visible to the dependent grid's griddepcontrol.wait
    asm volatile("griddepcontrol.launch_dependents;" ::: "memory");
}

// ---------------------------------------------------------------------------
// Kernel 2: symmetric tile writer.
//   - All 1024 blocks active via lower->upper remap (mirror-writer twin).
//   - A rows in registers (4 coalesced float4 LDGs), only B-tile in smem
//     (16 KB -> 8 CTAs/SM, warp-capped occupancy).
//   - Pointer-increment store addressing; __stcs streaming stores.
//   - PDL: waits on GEMM completion AFTER block setup.
// ---------------------------------------------------------------------------
__global__ void __launch_bounds__(256)
sym_writer_kernel(float* __restrict__ out)
{
    int bj = blockIdx.x;
    int bi = blockIdx.y;
    bool mirror = false;
    if (bi > bj) {                    // remap lower -> strict-upper twin
        bi = (NT - 1) - bi;
        bj = (NT - 1) - bj;
        mirror = true;
    }
    const bool diag = (bi == bj);
    const int i0 = bi * TS;
    const int j0 = bj * TS;

    __shared__ __align__(16) float sB[TS * NOUT];    // 16 KB

    const int tid = threadIdx.x;
    const int c   = (tid & 63) * 4;   // channel offset (float4 lane)
    const int ip  = tid >> 6;         // ii sub-index 0..3

    // Wait until the GEMM grid's writes to g_* are visible.
    asm volatile("griddepcontrol.wait;" ::: "memory");

    // ---- A rows into registers: ii = ob*4 + ip, coalesced float4 loads ----
    float4 aR[4];
    #pragma unroll
    for (int ob = 0; ob < 4; ob++) {
        int r = i0 + ob * 4 + ip;
        float4 a0 = *reinterpret_cast<const float4*>(&g_A0[r * NOUT + c]);
        float4 a1 = *reinterpret_cast<const float4*>(&g_A1[r * NOUT + c]);
        aR[ob] = make_float4(a0.x + a1.x, a0.y + a1.y, a0.z + a1.z, a0.w + a1.w);
    }

    // ---- B tile (B0+B1) into smem, float4 coalesced ----
    #pragma unroll
    for (int s = 0; s < 4; s++) {
        int idx = tid + s * 256;      // float4 slot 0..1023
        int r   = idx >> 6;           // row 0..15
        int cc  = (idx & 63) * 4;
        float4 b0 = *reinterpret_cast<const float4*>(&g_B0[(j0 + r) * NOUT + cc]);
        float4 b1 = *reinterpret_cast<const float4*>(&g_B1[(j0 + r) * NOUT + cc]);
        *reinterpret_cast<float4*>(&sB[r * NOUT + cc]) =
            make_float4(b0.x + b1.x, b0.y + b1.y, b0.z + b1.z, b0.w + b1.w);
    }
    __syncthreads();

    if (!diag) {
        const size_t stride = mirror ? (size_t)NNODES * NOUT : (size_t)NOUT;
        #pragma unroll
        for (int ob = 0; ob < 4; ob++) {
            const int ii = ob * 4 + ip;
            const int i  = i0 + ii;
            const float4 a = aR[ob];
            float* p = mirror
                ? &out[((size_t)j0 * NNODES + i) * NOUT + c]
                : &out[((size_t)i * NNODES + j0) * NOUT + c];
            #pragma unroll 4
            for (int jj = 0; jj < TS; jj++) {
                float4 bb = *reinterpret_cast<const float4*>(&sB[jj * NOUT + c]);
                float4 v  = make_float4(a.x + bb.x, a.y + bb.y,
                                        a.z + bb.z, a.w + bb.w);
                __stcs(reinterpret_cast<float4*>(p), v);
                p += stride;
            }
        }
    } else {
        // diagonal tile: single block writes both copies + zero diagonal
        #pragma unroll
        for (int ob = 0; ob < 4; ob++) {
            const int ii = ob * 4 + ip;
            const int i  = i0 + ii;
            const float4 a = aR[ob];
            float* pij = &out[((size_t)i * NNODES + (j0 + ii + 1)) * NOUT + c];
            float* pji = &out[((size_t)(j0 + ii + 1) * NNODES + i) * NOUT + c];
            for (int jj = ii + 1; jj < TS; jj++) {
                float4 bb = *reinterpret_cast<const float4*>(&sB[jj * NOUT + c]);
                float4 v  = make_float4(a.x + bb.x, a.y + bb.y,
                                        a.z + bb.z, a.w + bb.w);
                __stcs(reinterpret_cast<float4*>(pij), v);
                __stcs(reinterpret_cast<float4*>(pji), v);
                pij += NOUT;
                pji += (size_t)NNODES * NOUT;
            }
            __stcs(reinterpret_cast<float4*>(
                &out[((size_t)i * NNODES + i) * NOUT + c]),
                make_float4(0.f, 0.f, 0.f, 0.f));
        }
    }
}

extern "C" void kernel_launch(void* const* d_in, const int* in_sizes, int n_in,
                              void* d_out, int out_size)
{
    const float* x = (const float*)d_in[0];   // [512, 256]
    const float* W = (const float*)d_in[1];   // [256, 512]
    const float* b = (const float*)d_in[2];   // [256]
    float* out = (float*)d_out;               // [512, 512, 256]

    // Kernel 1: split-K partials (512 blocks x 128 threads)
    gemm_ab_kernel<<<dim3(8, 16, 4), 128>>>(x, W, b);

    // Kernel 2: symmetric writer, launched with PDL so its setup overlaps
    // the GEMM tail. griddepcontrol.wait inside orders the g_* reads.
    cudaLaunchConfig_t cfg = {};
    cfg.gridDim  = dim3(NT, NT, 1);
    cfg.blockDim = dim3(256, 1, 1);
    cfg.dynamicSmemBytes = 0;
    cfg.stream = 0;
    cudaLaunchAttribute attrs[1];
    attrs[0].id = cudaLaunchAttributeProgrammaticStreamSerialization;
    attrs[0].val.programmaticStreamSerializationAllowed = 1;
    cfg.attrs = attrs;
    cfg.numAttrs = 1;
    cudaLaunchKernelEx(&cfg, sym_writer_kernel, out);
}